// round 14
// baseline (speedup 1.0000x reference)
#include <cuda_runtime.h>
#include <math.h>
#include <stdint.h>

// MultiHeadAttention B=8 S=1024 HIDDEN=1024 HEADS=16 HEAD_DIM=64
// mma.sync tf32 path (tcgen05 unavailable: harness PTX target is sm_103, not sm_103a)
#define BATCH 8
#define SEQ 1024
#define HIDDEN 1024
#define HEADS 16
#define HEAD_DIM 64
#define MTOT (BATCH * SEQ)          // 8192
#define QKV_N (3 * HIDDEN)          // 3072

// scratch (__device__ globals: allocation-free rule)
__device__ float g_qkv[MTOT * QKV_N];     // 96 MB (tf32-rounded by GEMM1 epilogue)
__device__ float g_att[MTOT * HIDDEN];    // 32 MB (tf32-rounded)
__device__ float g_x  [MTOT * HIDDEN];    // tf32-rounded X
__device__ float g_w1t[QKV_N * HIDDEN];   // Wqkv^T [N,K], tf32-rounded
__device__ float g_w2t[HIDDEN * HIDDEN];  // Wo^T   [N,K], tf32-rounded

// ---------------------------------------------------------------------------
__device__ __forceinline__ uint32_t f2tf(float f) {
    uint32_t u; asm("cvt.rna.tf32.f32 %0, %1;" : "=r"(u) : "f"(f)); return u;
}
__device__ __forceinline__ uint32_t fbits(float f) { return __float_as_uint(f); }
__device__ __forceinline__ float ex2(float x) {
    float y; asm("ex2.approx.ftz.f32 %0, %1;" : "=f"(y) : "f"(x)); return y;
}

__device__ __forceinline__ void mma8(float* c, uint32_t a0, uint32_t a1, uint32_t a2, uint32_t a3,
                                     uint32_t b0, uint32_t b1) {
    asm volatile(
        "mma.sync.aligned.m16n8k8.row.col.f32.tf32.tf32.f32 "
        "{%0,%1,%2,%3},{%4,%5,%6,%7},{%8,%9},{%0,%1,%2,%3};"
        : "+f"(c[0]), "+f"(c[1]), "+f"(c[2]), "+f"(c[3])
        : "r"(a0), "r"(a1), "r"(a2), "r"(a3), "r"(b0), "r"(b1));
}

__device__ __forceinline__ void ldsm4(uint32_t* d, uint32_t a) {
    asm volatile("ldmatrix.sync.aligned.m8n8.x4.shared.b16 {%0,%1,%2,%3}, [%4];"
                 : "=r"(d[0]), "=r"(d[1]), "=r"(d[2]), "=r"(d[3]) : "r"(a));
}
__device__ __forceinline__ void ldsm2(uint32_t* d, uint32_t a) {
    asm volatile("ldmatrix.sync.aligned.m8n8.x2.shared.b16 {%0,%1}, [%2];"
                 : "=r"(d[0]), "=r"(d[1]) : "r"(a));
}

__device__ __forceinline__ void cp16(uint32_t dst, const void* src) {
    asm volatile("cp.async.cg.shared.global [%0], [%1], 16;" :: "r"(dst), "l"(src));
}
__device__ __forceinline__ void cp_commit() { asm volatile("cp.async.commit_group;"); }
template <int n> __device__ __forceinline__ void cp_wait() {
    asm volatile("cp.async.wait_group %0;" :: "n"(n));
}
__device__ __forceinline__ uint32_t smem_u32(const void* p) {
    return (uint32_t)__cvta_generic_to_shared(p);
}

// ---------------------------------------------------------------------------
// prep kernels
// ---------------------------------------------------------------------------
__global__ void k_round(const float* __restrict__ in, float* __restrict__ out, int n4) {
    int i = blockIdx.x * blockDim.x + threadIdx.x;
    if (i < n4) {
        float4 v = ((const float4*)in)[i];
        v.x = __uint_as_float(f2tf(v.x));
        v.y = __uint_as_float(f2tf(v.y));
        v.z = __uint_as_float(f2tf(v.z));
        v.w = __uint_as_float(f2tf(v.w));
        ((float4*)out)[i] = v;
    }
}

// in[R][C] -> out[C][R], tf32-rounded.  block (32,8), grid (C/32, R/32)
__global__ void k_transpose_tf(const float* __restrict__ in, float* __restrict__ out, int R, int C) {
    __shared__ float t[32][33];
    int c = blockIdx.x * 32 + threadIdx.x;
    int r0 = blockIdx.y * 32 + threadIdx.y;
#pragma unroll
    for (int i = 0; i < 32; i += 8)
        t[threadIdx.y + i][threadIdx.x] = in[(size_t)(r0 + i) * C + c];
    __syncthreads();
    int rr = blockIdx.y * 32 + threadIdx.x;
    int cc0 = blockIdx.x * 32 + threadIdx.y;
#pragma unroll
    for (int i = 0; i < 32; i += 8)
        out[(size_t)(cc0 + i) * R + rr] = __uint_as_float(f2tf(t[threadIdx.x][threadIdx.y + i]));
}

// ---------------------------------------------------------------------------
// tf32 GEMM via mma.sync + ldmatrix (R8/R12 config — validated 47.7% tensor):
// CTA 128x128, BK=16, 8 warps (warp tile 64x32), 4-stage cp.async ring,
// one __syncthreads per k-tile, 2 CTAs/SM (regs<=128).
// ---------------------------------------------------------------------------
#define GSTG_BYTES 20480
#define GEMM_SMEM (4 * GSTG_BYTES)    // 81920

template <int NTOT, bool ROUND>
__global__ void __launch_bounds__(256, 2) gemm_tc(const float* __restrict__ A,
                                                  const float* __restrict__ Bt,
                                                  const float* __restrict__ bias,
                                                  float* __restrict__ C) {
    extern __shared__ char smem[];
    const uint32_t sb = smem_u32(smem);
    const int tid = threadIdx.x;
    const int lane = tid & 31;
    const int warp = tid >> 5;
    const int bm = blockIdx.y * 128;
    const int bn = blockIdx.x * 128;
    const int wm = (warp & 1) * 64;
    const int wn = (warp >> 1) * 32;
    const int r  = lane >> 2;
    const int cc = lane & 3;
    const int K = HIDDEN;

    const int srow = tid >> 1;
    const int scol = (tid & 1) * 8;
    const float* Ag = A  + (size_t)(bm + srow) * K + scol;
    const float* Bg = Bt + (size_t)(bn + srow) * K + scol;
    const uint32_t sA = sb + (uint32_t)srow * 80 + (uint32_t)scol * 4;
    const uint32_t sB = sA + 10240;

    auto load = [&](int kb) {
        const uint32_t o = (uint32_t)(kb & 3) * GSTG_BYTES;
        const float* a = Ag + kb * 16;
        const float* b2 = Bg + kb * 16;
        cp16(sA + o,      a);
        cp16(sA + o + 16, a + 4);
        cp16(sB + o,      b2);
        cp16(sB + o + 16, b2 + 4);
    };

    float acc[4][4][4];
#pragma unroll
    for (int i = 0; i < 4; i++)
#pragma unroll
        for (int j = 0; j < 4; j++)
#pragma unroll
            for (int q = 0; q < 4; q++) acc[i][j][q] = 0.f;

    const uint32_t aLane = (uint32_t)(wm + (lane & 15)) * 80 + (uint32_t)(lane & 16);
    const uint32_t bLane = 10240 + (uint32_t)(wn + (lane & 7)) * 80 + (uint32_t)((lane & 8) * 2);

    load(0); cp_commit();
    load(1); cp_commit();
    load(2); cp_commit();

    const int NT = K / 16;   // 64
    for (int kb = 0; kb < NT; kb++) {
        cp_wait<2>();
        __syncthreads();
        if (kb + 3 < NT) load(kb + 3);
        cp_commit();

        const uint32_t st = sb + (uint32_t)(kb & 3) * GSTG_BYTES;
        const uint32_t Ab = st + aLane;
        const uint32_t Bb = st + bLane;
#pragma unroll
        for (int ks = 0; ks < 2; ks++) {
            uint32_t af[4][4], bf[4][2];
#pragma unroll
            for (int i = 0; i < 4; i++) ldsm4(af[i], Ab + i * 1280 + ks * 32);
#pragma unroll
            for (int j = 0; j < 4; j++) ldsm2(bf[j], Bb + j * 640 + ks * 32);
#pragma unroll
            for (int i = 0; i < 4; i++)
#pragma unroll
                for (int j = 0; j < 4; j++)
                    mma8(acc[i][j], af[i][0], af[i][1], af[i][2], af[i][3], bf[j][0], bf[j][1]);
        }
    }

    // epilogue: bias (+ optional tf32 round) + store
#pragma unroll
    for (int i = 0; i < 4; i++) {
        const int row0 = bm + wm + 16 * i + r;
#pragma unroll
        for (int j = 0; j < 4; j++) {
            const int col = bn + wn + 8 * j + 2 * cc;
            const float b0 = bias[col], b1 = bias[col + 1];
            float v00 = acc[i][j][0] + b0, v01 = acc[i][j][1] + b1;
            float v10 = acc[i][j][2] + b0, v11 = acc[i][j][3] + b1;
            if (ROUND) {
                v00 = __uint_as_float(f2tf(v00));
                v01 = __uint_as_float(f2tf(v01));
                v10 = __uint_as_float(f2tf(v10));
                v11 = __uint_as_float(f2tf(v11));
            }
            *(float2*)&C[(size_t)row0 * NTOT + col]       = make_float2(v00, v01);
            *(float2*)&C[(size_t)(row0 + 8) * NTOT + col] = make_float2(v10, v11);
        }
    }
}

// ---------------------------------------------------------------------------
// Flash attention, tf32 mma.sync. R13: 128 threads (4 warps), q-block 128,
// 32 q rows per warp (two m16 tiles) — K and V fragments loaded ONCE and
// used by BOTH tiles: crossbar bytes per MMA halved (attention is 9:1
// crossbar-bound). K/V streamed in 64-token chunks via cp.async double
// buffer; softmax in exp2 domain.
// ---------------------------------------------------------------------------
#define KROW 68
#define VROW 72
#define KBUF (64 * KROW)
#define VBUF (64 * VROW)
#define ATT_SMEM ((2 * KBUF + 2 * VBUF) * 4)   // 71680

__global__ void __launch_bounds__(128, 2) k_attention() {
    extern __shared__ float sm[];
    float* Kb = sm;
    float* Vb = sm + 2 * KBUF;

    const int tid  = threadIdx.x;
    const int lane = tid & 31;
    const int warp = tid >> 5;         // 0..3
    const int qt = blockIdx.x;         // 0..7
    const int h  = blockIdx.y;
    const int b  = blockIdx.z;
    const int r  = lane >> 2;
    const int c  = lane & 3;

    // ---- Q fragments for TWO m16 tiles (rows warp*32 + t*16 + {r,r+8}) ----
    const float qscale = 0.125f * 1.4426950408889634f;
    uint32_t qf[2][8][4];
    {
        const float* Qp = g_qkv + (size_t)(b * SEQ + qt * 128 + warp * 32) * QKV_N + h * HEAD_DIM;
#pragma unroll
        for (int t = 0; t < 2; t++)
#pragma unroll
            for (int ks = 0; ks < 8; ks++) {
                const float* Qt = Qp + (size_t)(t * 16) * QKV_N;
                qf[t][ks][0] = f2tf(Qt[(size_t)r       * QKV_N + 8 * ks + c    ] * qscale);
                qf[t][ks][1] = f2tf(Qt[(size_t)(r + 8) * QKV_N + 8 * ks + c    ] * qscale);
                qf[t][ks][2] = f2tf(Qt[(size_t)r       * QKV_N + 8 * ks + c + 4] * qscale);
                qf[t][ks][3] = f2tf(Qt[(size_t)(r + 8) * QKV_N + 8 * ks + c + 4] * qscale);
            }
    }

    // staging: thread = (row = tid>>1, half = tid&1); 8 cp16 K + 8 cp16 V
    const int srow = tid >> 1;
    const int sc0  = (tid & 1) * 32;
    const float* kbase = g_qkv + (size_t)(b * SEQ) * QKV_N + HIDDEN + h * HEAD_DIM + sc0;

    auto load_chunk = [&](int ct, int buf) {
        const float* kp = kbase + (size_t)(ct * 64 + srow) * QKV_N;
        const float* vp = kp + HIDDEN;
        const uint32_t kd = smem_u32(&Kb[buf * KBUF + srow * KROW + sc0]);
        const uint32_t vd = smem_u32(&Vb[buf * VBUF + srow * VROW + sc0]);
#pragma unroll
        for (int i = 0; i < 8; i++) cp16(kd + i * 16, kp + i * 4);
#pragma unroll
        for (int i = 0; i < 8; i++) cp16(vd + i * 16, vp + i * 4);
    };

    float m[2][2], l[2][2];
#pragma unroll
    for (int t = 0; t < 2; t++) { m[t][0] = m[t][1] = -INFINITY; l[t][0] = l[t][1] = 0.f; }
    float o[2][8][4];
#pragma unroll
    for (int t = 0; t < 2; t++)
#pragma unroll
        for (int j = 0; j < 8; j++)
#pragma unroll
            for (int q = 0; q < 4; q++) o[t][j][q] = 0.f;

    const uint32_t kLane = (uint32_t)(lane & 15) * (KROW * 4) + (uint32_t)(lane & 16);

    load_chunk(0, 0);
    cp_commit();

    for (int ct = 0; ct < 16; ct++) {
        const int buf = ct & 1;
        cp_wait<0>();
        __syncthreads();
        if (ct + 1 < 16) load_chunk(ct + 1, buf ^ 1);
        cp_commit();

        const float* Vs = &Vb[buf * VBUF];
        const uint32_t Kbase = smem_u32(&Kb[buf * KBUF]) + kLane;

        // ---- S = Q @ K^T : K frags shared across both q-tiles ----
        float s[2][8][4];
#pragma unroll
        for (int t = 0; t < 2; t++)
#pragma unroll
            for (int j = 0; j < 8; j++)
#pragma unroll
                for (int q = 0; q < 4; q++) s[t][j][q] = 0.f;

#pragma unroll
        for (int ks = 0; ks < 8; ks++) {
#pragma unroll
            for (int j2 = 0; j2 < 4; j2++) {
                uint32_t kq[4];
                ldsm4(kq, Kbase + (uint32_t)j2 * (16 * KROW * 4) + ks * 32);
#pragma unroll
                for (int t = 0; t < 2; t++) {
                    mma8(s[t][2 * j2],     qf[t][ks][0], qf[t][ks][1], qf[t][ks][2], qf[t][ks][3],
                         kq[0], kq[2]);
                    mma8(s[t][2 * j2 + 1], qf[t][ks][0], qf[t][ks][1], qf[t][ks][2], qf[t][ks][3],
                         kq[1], kq[3]);
                }
            }
        }

        // ---- online softmax (base-2), per tile ----
        float cor[2][2];
#pragma unroll
        for (int t = 0; t < 2; t++) {
            float mx0 = -INFINITY, mx1 = -INFINITY;
#pragma unroll
            for (int j = 0; j < 8; j++) {
                mx0 = fmaxf(mx0, fmaxf(s[t][j][0], s[t][j][1]));
                mx1 = fmaxf(mx1, fmaxf(s[t][j][2], s[t][j][3]));
            }
#pragma unroll
            for (int off = 1; off < 4; off <<= 1) {
                mx0 = fmaxf(mx0, __shfl_xor_sync(0xffffffffu, mx0, off));
                mx1 = fmaxf(mx1, __shfl_xor_sync(0xffffffffu, mx1, off));
            }
            const float nm0 = fmaxf(m[t][0], mx0), nm1 = fmaxf(m[t][1], mx1);
            cor[t][0] = ex2(m[t][0] - nm0); cor[t][1] = ex2(m[t][1] - nm1);
            m[t][0] = nm0; m[t][1] = nm1;
            float rs0 = 0.f, rs1 = 0.f;
#pragma unroll
            for (int j = 0; j < 8; j++) {
                s[t][j][0] = ex2(s[t][j][0] - nm0);
                s[t][j][1] = ex2(s[t][j][1] - nm0);
                s[t][j][2] = ex2(s[t][j][2] - nm1);
                s[t][j][3] = ex2(s[t][j][3] - nm1);
                rs0 += s[t][j][0] + s[t][j][1];
                rs1 += s[t][j][2] + s[t][j][3];
            }
#pragma unroll
            for (int off = 1; off < 4; off <<= 1) {
                rs0 += __shfl_xor_sync(0xffffffffu, rs0, off);
                rs1 += __shfl_xor_sync(0xffffffffu, rs1, off);
            }
            l[t][0] = l[t][0] * cor[t][0] + rs0;
            l[t][1] = l[t][1] * cor[t][1] + rs1;
#pragma unroll
            for (int j = 0; j < 8; j++) {
                o[t][j][0] *= cor[t][0]; o[t][j][1] *= cor[t][0];
                o[t][j][2] *= cor[t][1]; o[t][j][3] *= cor[t][1];
            }
        }

        // ---- O += P @ V : V frags shared across both q-tiles ----
        const int sbase = lane & ~3;
        const int src1 = sbase | (c >> 1);
        const int src2 = sbase | 2 | (c >> 1);
        const bool odd = (c & 1);
#pragma unroll
        for (int kt = 0; kt < 8; kt++) {
            uint32_t A0[2], A1[2], A2[2], A3[2];
#pragma unroll
            for (int t = 0; t < 2; t++) {
                uint32_t p0 = f2tf(s[t][kt][0]), p1 = f2tf(s[t][kt][1]);
                uint32_t p2 = f2tf(s[t][kt][2]), p3 = f2tf(s[t][kt][3]);
                uint32_t x0 = __shfl_sync(0xffffffffu, p0, src1);
                uint32_t x1 = __shfl_sync(0xffffffffu, p1, src1);
                uint32_t x2 = __shfl_sync(0xffffffffu, p2, src1);
                uint32_t x3 = __shfl_sync(0xffffffffu, p3, src1);
                uint32_t y0 = __shfl_sync(0xffffffffu, p0, src2);
                uint32_t y1 = __shfl_sync(0xffffffffu, p1, src2);
                uint32_t y2 = __shfl_sync(0xffffffffu, p2, src2);
                uint32_t y3 = __shfl_sync(0xffffffffu, p3, src2);
                A0[t] = odd ? x1 : x0;
                A1[t] = odd ? x3 : x2;
                A2[t] = odd ? y1 : y0;
                A3[t] = odd ? y3 : y2;
            }
#pragma unroll
            for (int j = 0; j < 8; j++) {
                uint32_t b0 = fbits(Vs[(8 * kt + c    ) * VROW + 8 * j + r]);
                uint32_t b1 = fbits(Vs[(8 * kt + c + 4) * VROW + 8 * j + r]);
                mma8(o[0][j], A0[0], A1[0], A2[0], A3[0], b0, b1);
                mma8(o[1][j], A0[1], A1[1], A2[1], A3[1], b0, b1);
            }
        }
    }

    // ---- normalize, tf32-round (feeds GEMM2), store ----
#pragma unroll
    for (int t = 0; t < 2; t++) {
        const float inv0 = 1.f / l[t][0], inv1 = 1.f / l[t][1];
        const size_t gq = (size_t)(b * SEQ + qt * 128 + warp * 32 + t * 16);
#pragma unroll
        for (int j = 0; j < 8; j++) {
            const int col = h * HEAD_DIM + 8 * j + 2 * c;
            float2 v0, v1;
            v0.x = __uint_as_float(f2tf(o[t][j][0] * inv0));
            v0.y = __uint_as_float(f2tf(o[t][j][1] * inv0));
            v1.x = __uint_as_float(f2tf(o[t][j][2] * inv1));
            v1.y = __uint_as_float(f2tf(o[t][j][3] * inv1));
            *(float2*)&g_att[(gq + r) * HIDDEN + col]     = v0;
            *(float2*)&g_att[(gq + r + 8) * HIDDEN + col] = v1;
        }
    }
}

// ---------------------------------------------------------------------------
extern "C" void kernel_launch(void* const* d_in, const int* in_sizes, int n_in,
                              void* d_out, int out_size) {
    const float* query = (const float*)d_in[0];
    const float* w_qkv = (const float*)d_in[1];
    const float* b_qkv = (const float*)d_in[2];
    const float* w_o   = (const float*)d_in[3];
    const float* b_o   = (const float*)d_in[4];
    float* out = (float*)d_out;

    float *gx, *gw1t, *gw2t, *gqkv, *gatt;
    cudaGetSymbolAddress((void**)&gx,   g_x);
    cudaGetSymbolAddress((void**)&gw1t, g_w1t);
    cudaGetSymbolAddress((void**)&gw2t, g_w2t);
    cudaGetSymbolAddress((void**)&gqkv, g_qkv);
    cudaGetSymbolAddress((void**)&gatt, g_att);

    cudaFuncSetAttribute(gemm_tc<QKV_N, true>,   cudaFuncAttributeMaxDynamicSharedMemorySize, GEMM_SMEM);
    cudaFuncSetAttribute(gemm_tc<HIDDEN, false>, cudaFuncAttributeMaxDynamicSharedMemorySize, GEMM_SMEM);
    cudaFuncSetAttribute(k_attention,            cudaFuncAttributeMaxDynamicSharedMemorySize, ATT_SMEM);

    // prep: round X; transpose+round weights
    {
        int n4x = MTOT * HIDDEN / 4;
        k_round<<<(n4x + 255) / 256, 256>>>(query, gx, n4x);
        dim3 tb(32, 8);
        k_transpose_tf<<<dim3(QKV_N / 32, HIDDEN / 32), tb>>>(w_qkv, gw1t, HIDDEN, QKV_N);
        k_transpose_tf<<<dim3(HIDDEN / 32, HIDDEN / 32), tb>>>(w_o, gw2t, HIDDEN, HIDDEN);
    }

    // QKV GEMM (rounds output to tf32 for attention)
    gemm_tc<QKV_N, true><<<dim3(QKV_N / 128, MTOT / 128), 256, GEMM_SMEM>>>(gx, gw1t, b_qkv, gqkv);

    // flash attention (128 threads, 4 warps x 32 q-rows)
    k_attention<<<dim3(SEQ / 128, HEADS, BATCH), 128, ATT_SMEM>>>();

    // output GEMM
    gemm_tc<HIDDEN, false><<<dim3(HIDDEN / 128, MTOT / 128), 256, GEMM_SMEM>>>(gatt, gw2t, b_o, out);
}

// round 16
// speedup vs baseline: 2.0153x; 2.0153x over previous
#include <cuda_runtime.h>
#include <cuda_fp16.h>
#include <math.h>
#include <stdint.h>

// MultiHeadAttention B=8 S=1024 HIDDEN=1024 HEADS=16 HEAD_DIM=64
// fp16-operand mma.sync path (fp16 mantissa == tf32 mantissa; half the bytes,
// double the K per MMA). fp32 accumulate everywhere.
#define BATCH 8
#define SEQ 1024
#define HIDDEN 1024
#define HEADS 16
#define HEAD_DIM 64
#define MTOT (BATCH * SEQ)          // 8192
#define QKV_N (3 * HIDDEN)          // 3072

// scratch (__device__ globals: allocation-free rule)
__device__ __half g_qkv[MTOT * QKV_N];     // 48 MB (fp16 out of GEMM1)
__device__ __half g_att[MTOT * HIDDEN];    // 16 MB
__device__ __half g_x  [MTOT * HIDDEN];    // fp16 X
__device__ __half g_w1t[QKV_N * HIDDEN];   // Wqkv^T [N,K]
__device__ __half g_w2t[HIDDEN * HIDDEN];  // Wo^T   [N,K]

// ---------------------------------------------------------------------------
__device__ __forceinline__ float ex2(float x) {
    float y; asm("ex2.approx.ftz.f32 %0, %1;" : "=f"(y) : "f"(x)); return y;
}
__device__ __forceinline__ uint32_t packh2(float lo, float hi) {
    __half2 h = __floats2half2_rn(lo, hi);
    return *reinterpret_cast<uint32_t*>(&h);
}

// m16n8k16 fp16 mma, fp32 accumulate
__device__ __forceinline__ void mma16(float* c, uint32_t a0, uint32_t a1, uint32_t a2, uint32_t a3,
                                      uint32_t b0, uint32_t b1) {
    asm volatile(
        "mma.sync.aligned.m16n8k16.row.col.f32.f16.f16.f32 "
        "{%0,%1,%2,%3},{%4,%5,%6,%7},{%8,%9},{%0,%1,%2,%3};"
        : "+f"(c[0]), "+f"(c[1]), "+f"(c[2]), "+f"(c[3])
        : "r"(a0), "r"(a1), "r"(a2), "r"(a3), "r"(b0), "r"(b1));
}

__device__ __forceinline__ void ldsm4(uint32_t* d, uint32_t a) {
    asm volatile("ldmatrix.sync.aligned.m8n8.x4.shared.b16 {%0,%1,%2,%3}, [%4];"
                 : "=r"(d[0]), "=r"(d[1]), "=r"(d[2]), "=r"(d[3]) : "r"(a));
}
__device__ __forceinline__ void ldsm2(uint32_t* d, uint32_t a) {
    asm volatile("ldmatrix.sync.aligned.m8n8.x2.shared.b16 {%0,%1}, [%2];"
                 : "=r"(d[0]), "=r"(d[1]) : "r"(a));
}
__device__ __forceinline__ void ldsm4t(uint32_t* d, uint32_t a) {
    asm volatile("ldmatrix.sync.aligned.m8n8.x4.trans.shared.b16 {%0,%1,%2,%3}, [%4];"
                 : "=r"(d[0]), "=r"(d[1]), "=r"(d[2]), "=r"(d[3]) : "r"(a));
}

__device__ __forceinline__ void cp16(uint32_t dst, const void* src) {
    asm volatile("cp.async.cg.shared.global [%0], [%1], 16;" :: "r"(dst), "l"(src));
}
__device__ __forceinline__ void cp_commit() { asm volatile("cp.async.commit_group;"); }
template <int n> __device__ __forceinline__ void cp_wait() {
    asm volatile("cp.async.wait_group %0;" :: "n"(n));
}
__device__ __forceinline__ uint32_t smem_u32(const void* p) {
    return (uint32_t)__cvta_generic_to_shared(p);
}

// ---------------------------------------------------------------------------
// prep kernels
// ---------------------------------------------------------------------------
__global__ void k_cvt_half(const float* __restrict__ in, __half* __restrict__ out, int n4) {
    int i = blockIdx.x * blockDim.x + threadIdx.x;
    if (i < n4) {
        float4 v = ((const float4*)in)[i];
        uint2 o;
        o.x = packh2(v.x, v.y);
        o.y = packh2(v.z, v.w);
        ((uint2*)out)[i] = o;
    }
}

// in[R][C] fp32 -> out[C][R] fp16.  block (32,8), grid (C/32, R/32)
__global__ void k_transpose_h(const float* __restrict__ in, __half* __restrict__ out, int R, int C) {
    __shared__ float t[32][33];
    int c = blockIdx.x * 32 + threadIdx.x;
    int r0 = blockIdx.y * 32 + threadIdx.y;
#pragma unroll
    for (int i = 0; i < 32; i += 8)
        t[threadIdx.y + i][threadIdx.x] = in[(size_t)(r0 + i) * C + c];
    __syncthreads();
    int rr = blockIdx.y * 32 + threadIdx.x;
    int cc0 = blockIdx.x * 32 + threadIdx.y;
#pragma unroll
    for (int i = 0; i < 32; i += 8)
        out[(size_t)(cc0 + i) * R + rr] = __float2half_rn(t[threadIdx.x][threadIdx.y + i]);
}

// ---------------------------------------------------------------------------
// fp16 GEMM via mma.sync m16n8k16 + ldmatrix: C = A[M,1024] @ Bt[N,1024]^T + bias
// CTA 128x128, BK=32 (2 x k16), 8 warps (warp tile 64x32), 4-stage cp.async,
// one __syncthreads per k-tile, 2 CTAs/SM (regs<=128).
// smem rows: 32 halfs (64B) + 16B pad = 80B; conflict-free ldmatrix
// (row starts at banks 20*i mod 32: all 8 phases disjoint).
// Stage = (128+128)*80 = 20480 B; 4 stages = 80 KB.  NT = 1024/32 = 32.
// ---------------------------------------------------------------------------
#define GSTG_BYTES 20480
#define GEMM_SMEM (4 * GSTG_BYTES)    // 81920

template <int NTOT, bool HALF_OUT>
__global__ void __launch_bounds__(256, 2) gemm_h(const __half* __restrict__ A,
                                                 const __half* __restrict__ Bt,
                                                 const float* __restrict__ bias,
                                                 void* __restrict__ Cp) {
    extern __shared__ char smem[];
    const uint32_t sb = smem_u32(smem);
    const int tid = threadIdx.x;
    const int lane = tid & 31;
    const int warp = tid >> 5;
    const int bm = blockIdx.y * 128;
    const int bn = blockIdx.x * 128;
    const int wm = (warp & 1) * 64;
    const int wn = (warp >> 1) * 32;
    const int r  = lane >> 2;
    const int cc = lane & 3;
    const int K = HIDDEN;

    // staging: thread covers 16 halfs (32B) of one A row and one B row
    const int srow = tid >> 1;
    const int scol = (tid & 1) * 16;           // halfs
    const __half* Ag = A  + (size_t)(bm + srow) * K + scol;
    const __half* Bg = Bt + (size_t)(bn + srow) * K + scol;
    const uint32_t sA = sb + (uint32_t)srow * 80 + (uint32_t)(tid & 1) * 32;
    const uint32_t sB = sA + 10240;

    auto load = [&](int kb) {
        const uint32_t o = (uint32_t)(kb & 3) * GSTG_BYTES;
        const __half* a = Ag + kb * 32;
        const __half* b2 = Bg + kb * 32;
        cp16(sA + o,      a);
        cp16(sA + o + 16, a + 8);
        cp16(sB + o,      b2);
        cp16(sB + o + 16, b2 + 8);
    };

    float acc[4][4][4];
#pragma unroll
    for (int i = 0; i < 4; i++)
#pragma unroll
        for (int j = 0; j < 4; j++)
#pragma unroll
            for (int q = 0; q < 4; q++) acc[i][j][q] = 0.f;

    // ldmatrix lane addresses (bytes)
    const uint32_t aLane = (uint32_t)(wm + (lane & 15)) * 80 + (uint32_t)(lane & 16);
    const uint32_t bLane = 10240 + (uint32_t)(wn + (lane & 7)) * 80 + (uint32_t)((lane & 8) * 2);

    load(0); cp_commit();
    load(1); cp_commit();
    load(2); cp_commit();

    const int NT = K / 32;   // 32
    for (int kb = 0; kb < NT; kb++) {
        cp_wait<2>();
        __syncthreads();
        if (kb + 3 < NT) load(kb + 3);
        cp_commit();

        const uint32_t st = sb + (uint32_t)(kb & 3) * GSTG_BYTES;
        const uint32_t Ab = st + aLane;
        const uint32_t Bb = st + bLane;
#pragma unroll
        for (int ks = 0; ks < 2; ks++) {        // k16 steps
            uint32_t af[4][4], bf[4][2];
#pragma unroll
            for (int i = 0; i < 4; i++) ldsm4(af[i], Ab + i * 1280 + ks * 32);
#pragma unroll
            for (int j = 0; j < 4; j++) ldsm2(bf[j], Bb + j * 640 + ks * 32);
#pragma unroll
            for (int i = 0; i < 4; i++)
#pragma unroll
                for (int j = 0; j < 4; j++)
                    mma16(acc[i][j], af[i][0], af[i][1], af[i][2], af[i][3], bf[j][0], bf[j][1]);
        }
    }

    // epilogue: bias + store (half2 or float2)
#pragma unroll
    for (int i = 0; i < 4; i++) {
        const int row0 = bm + wm + 16 * i + r;
#pragma unroll
        for (int j = 0; j < 4; j++) {
            const int col = bn + wn + 8 * j + 2 * cc;
            const float b0 = bias[col], b1 = bias[col + 1];
            float v00 = acc[i][j][0] + b0, v01 = acc[i][j][1] + b1;
            float v10 = acc[i][j][2] + b0, v11 = acc[i][j][3] + b1;
            if (HALF_OUT) {
                __half* C = (__half*)Cp;
                *(uint32_t*)&C[(size_t)row0 * NTOT + col]       = packh2(v00, v01);
                *(uint32_t*)&C[(size_t)(row0 + 8) * NTOT + col] = packh2(v10, v11);
            } else {
                float* C = (float*)Cp;
                *(float2*)&C[(size_t)row0 * NTOT + col]       = make_float2(v00, v01);
                *(float2*)&C[(size_t)(row0 + 8) * NTOT + col] = make_float2(v10, v11);
            }
        }
    }
}

// ---------------------------------------------------------------------------
// Flash attention, fp16 mma.sync m16n8k16. 256 threads (8 warps), q-block 128
// (16 rows/warp), K/V 64-token chunks, cp.async double buffer.
// K frags: ldmatrix.x4 ([token][dim] rows). V frags: ldmatrix.x4.trans
// ([token][dim] rows -> B-frag n=dim, k=token). P D-frag -> A-frag needs NO
// shuffles in fp16 (half2(c0,c1) is exactly the A-frag register).
// smem row stride 72 halfs (144B): ldsm phases start at banks 4i — disjoint.
// ---------------------------------------------------------------------------
#define KROWH 72
#define KBUFH (64 * KROWH)

__global__ void __launch_bounds__(256, 2) k_attention() {
    __shared__ __half Ks[2][64][KROWH];
    __shared__ __half Vs[2][64][KROWH];

    const int tid  = threadIdx.x;
    const int lane = tid & 31;
    const int warp = tid >> 5;
    const int qt = blockIdx.x;
    const int h  = blockIdx.y;
    const int b  = blockIdx.z;
    const int r  = lane >> 2;
    const int c  = lane & 3;

    // ---- Q fragments (scaled by 1/8*log2e, fp16) ----
    const float qscale = 0.125f * 1.4426950408889634f;
    uint32_t qf[4][4];
    {
        const __half* Qp = g_qkv + (size_t)(b * SEQ + qt * 128 + warp * 16) * QKV_N + h * HEAD_DIM;
#pragma unroll
        for (int ks = 0; ks < 4; ks++) {
#pragma unroll
            for (int half8 = 0; half8 < 2; half8++) {     // k sub-block 0 / +8
                const int kc = 16 * ks + 8 * half8 + 2 * c;
                float2 f0 = __half22float2(*(const __half2*)&Qp[(size_t)r       * QKV_N + kc]);
                float2 f1 = __half22float2(*(const __half2*)&Qp[(size_t)(r + 8) * QKV_N + kc]);
                qf[ks][2 * half8 + 0] = packh2(f0.x * qscale, f0.y * qscale);
                qf[ks][2 * half8 + 1] = packh2(f1.x * qscale, f1.y * qscale);
            }
        }
    }

    // staging: thread -> (row = tid>>2, 16-half segment = tid&3)
    const int srow = tid >> 2;
    const int sc0  = (tid & 3) * 16;
    const __half* kbase = g_qkv + (size_t)(b * SEQ) * QKV_N + HIDDEN + h * HEAD_DIM + sc0;

    auto load_chunk = [&](int ct, int buf) {
        const __half* kp = kbase + (size_t)(ct * 64 + srow) * QKV_N;
        const __half* vp = kp + HIDDEN;
        const uint32_t kd = smem_u32(&Ks[buf][srow][sc0]);
        const uint32_t vd = smem_u32(&Vs[buf][srow][sc0]);
        cp16(kd,      kp);
        cp16(kd + 16, kp + 8);
        cp16(vd,      vp);
        cp16(vd + 16, vp + 8);
    };

    float m0 = -INFINITY, m1 = -INFINITY, l0 = 0.f, l1 = 0.f;
    float o[8][4];
#pragma unroll
    for (int j = 0; j < 8; j++)
#pragma unroll
        for (int q = 0; q < 4; q++) o[j][q] = 0.f;

    // ldmatrix lane offsets (bytes); row stride 144B
    const uint32_t lmLane = (uint32_t)(lane & 15) * 144 + (uint32_t)(lane & 16);

    load_chunk(0, 0);
    cp_commit();

    for (int ct = 0; ct < 16; ct++) {
        const int buf = ct & 1;
        cp_wait<0>();
        __syncthreads();
        if (ct + 1 < 16) load_chunk(ct + 1, buf ^ 1);
        cp_commit();

        const uint32_t Kbase = smem_u32(&Ks[buf][0][0]) + lmLane;
        const uint32_t Vbase = smem_u32(&Vs[buf][0][0]) + lmLane;

        // ---- S = Q @ K^T : 4 k16 steps x 8 token n-tiles ----
        float s[8][4];
#pragma unroll
        for (int j = 0; j < 8; j++)
#pragma unroll
            for (int q = 0; q < 4; q++) s[j][q] = 0.f;

#pragma unroll
        for (int ks = 0; ks < 4; ks++) {
#pragma unroll
            for (int j2 = 0; j2 < 4; j2++) {
                uint32_t kq[4];
                ldsm4(kq, Kbase + (uint32_t)j2 * (16 * 144) + ks * 32);
                mma16(s[2 * j2],     qf[ks][0], qf[ks][1], qf[ks][2], qf[ks][3], kq[0], kq[2]);
                mma16(s[2 * j2 + 1], qf[ks][0], qf[ks][1], qf[ks][2], qf[ks][3], kq[1], kq[3]);
            }
        }

        // ---- online softmax (base-2) ----
        float mx0 = -INFINITY, mx1 = -INFINITY;
#pragma unroll
        for (int j = 0; j < 8; j++) {
            mx0 = fmaxf(mx0, fmaxf(s[j][0], s[j][1]));
            mx1 = fmaxf(mx1, fmaxf(s[j][2], s[j][3]));
        }
#pragma unroll
        for (int off = 1; off < 4; off <<= 1) {
            mx0 = fmaxf(mx0, __shfl_xor_sync(0xffffffffu, mx0, off));
            mx1 = fmaxf(mx1, __shfl_xor_sync(0xffffffffu, mx1, off));
        }
        const float nm0 = fmaxf(m0, mx0), nm1 = fmaxf(m1, mx1);
        const float cor0 = ex2(m0 - nm0), cor1 = ex2(m1 - nm1);
        m0 = nm0; m1 = nm1;
        float rs0 = 0.f, rs1 = 0.f;
#pragma unroll
        for (int j = 0; j < 8; j++) {
            s[j][0] = ex2(s[j][0] - nm0);
            s[j][1] = ex2(s[j][1] - nm0);
            s[j][2] = ex2(s[j][2] - nm1);
            s[j][3] = ex2(s[j][3] - nm1);
            rs0 += s[j][0] + s[j][1];
            rs1 += s[j][2] + s[j][3];
        }
#pragma unroll
        for (int off = 1; off < 4; off <<= 1) {
            rs0 += __shfl_xor_sync(0xffffffffu, rs0, off);
            rs1 += __shfl_xor_sync(0xffffffffu, rs1, off);
        }
        l0 = l0 * cor0 + rs0;
        l1 = l1 * cor1 + rs1;
#pragma unroll
        for (int j = 0; j < 8; j++) {
            o[j][0] *= cor0; o[j][1] *= cor0;
            o[j][2] *= cor1; o[j][3] *= cor1;
        }

        // ---- O += P @ V : A-frags packed from D-frags (no shuffles) ----
#pragma unroll
        for (int kt = 0; kt < 4; kt++) {         // 16 tokens each
            const uint32_t a0 = packh2(s[2 * kt][0],     s[2 * kt][1]);
            const uint32_t a1 = packh2(s[2 * kt][2],     s[2 * kt][3]);
            const uint32_t a2 = packh2(s[2 * kt + 1][0], s[2 * kt + 1][1]);
            const uint32_t a3 = packh2(s[2 * kt + 1][2], s[2 * kt + 1][3]);
#pragma unroll
            for (int d4 = 0; d4 < 4; d4++) {     // 16 dims each
                uint32_t vq[4];
                ldsm4t(vq, Vbase + (uint32_t)kt * (16 * 144) + d4 * 32);
                mma16(o[2 * d4],     a0, a1, a2, a3, vq[0], vq[1]);
                mma16(o[2 * d4 + 1], a0, a1, a2, a3, vq[2], vq[3]);
            }
        }
    }

    // ---- normalize, store fp16 (feeds GEMM2) ----
    const float inv0 = 1.f / l0, inv1 = 1.f / l1;
    const size_t gq = (size_t)(b * SEQ + qt * 128 + warp * 16);
#pragma unroll
    for (int j = 0; j < 8; j++) {
        const int col = h * HEAD_DIM + 8 * j + 2 * c;
        *(uint32_t*)&g_att[(gq + r) * HIDDEN + col]     = packh2(o[j][0] * inv0, o[j][1] * inv0);
        *(uint32_t*)&g_att[(gq + r + 8) * HIDDEN + col] = packh2(o[j][2] * inv1, o[j][3] * inv1);
    }
}

// ---------------------------------------------------------------------------
extern "C" void kernel_launch(void* const* d_in, const int* in_sizes, int n_in,
                              void* d_out, int out_size) {
    const float* query = (const float*)d_in[0];
    const float* w_qkv = (const float*)d_in[1];
    const float* b_qkv = (const float*)d_in[2];
    const float* w_o   = (const float*)d_in[3];
    const float* b_o   = (const float*)d_in[4];
    float* out = (float*)d_out;

    __half *gx, *gw1t, *gw2t, *gqkv, *gatt;
    cudaGetSymbolAddress((void**)&gx,   g_x);
    cudaGetSymbolAddress((void**)&gw1t, g_w1t);
    cudaGetSymbolAddress((void**)&gw2t, g_w2t);
    cudaGetSymbolAddress((void**)&gqkv, g_qkv);
    cudaGetSymbolAddress((void**)&gatt, g_att);

    cudaFuncSetAttribute(gemm_h<QKV_N, true>,   cudaFuncAttributeMaxDynamicSharedMemorySize, GEMM_SMEM);
    cudaFuncSetAttribute(gemm_h<HIDDEN, false>, cudaFuncAttributeMaxDynamicSharedMemorySize, GEMM_SMEM);

    // prep: cvt X; transpose+cvt weights
    {
        int n4x = MTOT * HIDDEN / 4;
        k_cvt_half<<<(n4x + 255) / 256, 256>>>(query, gx, n4x);
        dim3 tb(32, 8);
        k_transpose_h<<<dim3(QKV_N / 32, HIDDEN / 32), tb>>>(w_qkv, gw1t, HIDDEN, QKV_N);
        k_transpose_h<<<dim3(HIDDEN / 32, HIDDEN / 32), tb>>>(w_o, gw2t, HIDDEN, HIDDEN);
    }

    // QKV GEMM (fp16 out -> feeds attention directly)
    gemm_h<QKV_N, true><<<dim3(QKV_N / 128, MTOT / 128), 256, GEMM_SMEM>>>(gx, gw1t, b_qkv, gqkv);

    // flash attention
    k_attention<<<dim3(SEQ / 128, HEADS, BATCH), 256>>>();

    // output GEMM (fp32 out)
    gemm_h<HIDDEN, false><<<dim3(HIDDEN / 128, MTOT / 128), 256, GEMM_SMEM>>>(gatt, gw2t, b_o, out);
}

// round 17
// speedup vs baseline: 2.0245x; 1.0046x over previous
#include <cuda_runtime.h>
#include <cuda_fp16.h>
#include <math.h>
#include <stdint.h>

// MultiHeadAttention B=8 S=1024 HIDDEN=1024 HEADS=16 HEAD_DIM=64
// fp16-operand mma.sync path; R17: cross-barrier fragment pipelining in GEMM.
#define BATCH 8
#define SEQ 1024
#define HIDDEN 1024
#define HEADS 16
#define HEAD_DIM 64
#define MTOT (BATCH * SEQ)          // 8192
#define QKV_N (3 * HIDDEN)          // 3072

// scratch (__device__ globals: allocation-free rule)
__device__ __half g_qkv[MTOT * QKV_N];     // 48 MB
__device__ __half g_att[MTOT * HIDDEN];    // 16 MB
__device__ __half g_x  [MTOT * HIDDEN];
__device__ __half g_w1t[QKV_N * HIDDEN];   // Wqkv^T [N,K]
__device__ __half g_w2t[HIDDEN * HIDDEN];  // Wo^T   [N,K]

// ---------------------------------------------------------------------------
__device__ __forceinline__ float ex2(float x) {
    float y; asm("ex2.approx.ftz.f32 %0, %1;" : "=f"(y) : "f"(x)); return y;
}
__device__ __forceinline__ uint32_t packh2(float lo, float hi) {
    __half2 h = __floats2half2_rn(lo, hi);
    return *reinterpret_cast<uint32_t*>(&h);
}

__device__ __forceinline__ void mma16(float* c, uint32_t a0, uint32_t a1, uint32_t a2, uint32_t a3,
                                      uint32_t b0, uint32_t b1) {
    asm volatile(
        "mma.sync.aligned.m16n8k16.row.col.f32.f16.f16.f32 "
        "{%0,%1,%2,%3},{%4,%5,%6,%7},{%8,%9},{%0,%1,%2,%3};"
        : "+f"(c[0]), "+f"(c[1]), "+f"(c[2]), "+f"(c[3])
        : "r"(a0), "r"(a1), "r"(a2), "r"(a3), "r"(b0), "r"(b1));
}

__device__ __forceinline__ void ldsm4(uint32_t* d, uint32_t a) {
    asm volatile("ldmatrix.sync.aligned.m8n8.x4.shared.b16 {%0,%1,%2,%3}, [%4];"
                 : "=r"(d[0]), "=r"(d[1]), "=r"(d[2]), "=r"(d[3]) : "r"(a));
}
__device__ __forceinline__ void ldsm4t(uint32_t* d, uint32_t a) {
    asm volatile("ldmatrix.sync.aligned.m8n8.x4.trans.shared.b16 {%0,%1,%2,%3}, [%4];"
                 : "=r"(d[0]), "=r"(d[1]), "=r"(d[2]), "=r"(d[3]) : "r"(a));
}

__device__ __forceinline__ void cp16(uint32_t dst, const void* src) {
    asm volatile("cp.async.cg.shared.global [%0], [%1], 16;" :: "r"(dst), "l"(src));
}
__device__ __forceinline__ void cp_commit() { asm volatile("cp.async.commit_group;"); }
template <int n> __device__ __forceinline__ void cp_wait() {
    asm volatile("cp.async.wait_group %0;" :: "n"(n));
}
__device__ __forceinline__ uint32_t smem_u32(const void* p) {
    return (uint32_t)__cvta_generic_to_shared(p);
}

// ---------------------------------------------------------------------------
// prep kernels
// ---------------------------------------------------------------------------
__global__ void k_cvt_half(const float* __restrict__ in, __half* __restrict__ out, int n4) {
    int i = blockIdx.x * blockDim.x + threadIdx.x;
    if (i < n4) {
        float4 v = ((const float4*)in)[i];
        uint2 o;
        o.x = packh2(v.x, v.y);
        o.y = packh2(v.z, v.w);
        ((uint2*)out)[i] = o;
    }
}

__global__ void k_transpose_h(const float* __restrict__ in, __half* __restrict__ out, int R, int C) {
    __shared__ float t[32][33];
    int c = blockIdx.x * 32 + threadIdx.x;
    int r0 = blockIdx.y * 32 + threadIdx.y;
#pragma unroll
    for (int i = 0; i < 32; i += 8)
        t[threadIdx.y + i][threadIdx.x] = in[(size_t)(r0 + i) * C + c];
    __syncthreads();
    int rr = blockIdx.y * 32 + threadIdx.x;
    int cc0 = blockIdx.x * 32 + threadIdx.y;
#pragma unroll
    for (int i = 0; i < 32; i += 8)
        out[(size_t)(cc0 + i) * R + rr] = __float2half_rn(t[threadIdx.x][threadIdx.y + i]);
}

// ---------------------------------------------------------------------------
// fp16 GEMM, R17: cross-barrier fragment pipeline.
// CTA 128x128, BK=32 (2 x k16), 8 warps (warp 64x32), 4-stage cp.async ring.
// Iter kb: wait<1> (completes group kb+1) -> barrier (publishes stage kb+1,
// licenses overwrite of stage kb-1) -> load(kb+3) -> ldsm ks1(stage kb) ->
// mma ks0 (frags prefetched last iter) -> mma ks1 -> prefetch ks0(stage kb+1).
// MMA ks0 is independent of the ks1 LDSMs: crossbar and tensor overlap.
// ---------------------------------------------------------------------------
#define GSTG_BYTES 20480
#define GEMM_SMEM (4 * GSTG_BYTES)    // 81920

template <int NTOT, bool HALF_OUT>
__global__ void __launch_bounds__(256, 2) gemm_h(const __half* __restrict__ A,
                                                 const __half* __restrict__ Bt,
                                                 const float* __restrict__ bias,
                                                 void* __restrict__ Cp) {
    extern __shared__ char smem[];
    const uint32_t sb = smem_u32(smem);
    const int tid = threadIdx.x;
    const int lane = tid & 31;
    const int warp = tid >> 5;
    const int bm = blockIdx.y * 128;
    const int bn = blockIdx.x * 128;
    const int wm = (warp & 1) * 64;
    const int wn = (warp >> 1) * 32;
    const int r  = lane >> 2;
    const int cc = lane & 3;
    const int K = HIDDEN;

    // staging: thread covers 16 halfs (32B) of one A row and one B row
    const int srow = tid >> 1;
    const __half* Ag = A  + (size_t)(bm + srow) * K + (tid & 1) * 16;
    const __half* Bg = Bt + (size_t)(bn + srow) * K + (tid & 1) * 16;
    const uint32_t sA = sb + (uint32_t)srow * 80 + (uint32_t)(tid & 1) * 32;
    const uint32_t sB = sA + 10240;

    auto load = [&](int kb) {
        const uint32_t o = (uint32_t)(kb & 3) * GSTG_BYTES;
        const __half* a = Ag + kb * 32;
        const __half* b2 = Bg + kb * 32;
        cp16(sA + o,      a);
        cp16(sA + o + 16, a + 8);
        cp16(sB + o,      b2);
        cp16(sB + o + 16, b2 + 8);
    };

    float acc[4][4][4];
#pragma unroll
    for (int i = 0; i < 4; i++)
#pragma unroll
        for (int j = 0; j < 4; j++)
#pragma unroll
            for (int q = 0; q < 4; q++) acc[i][j][q] = 0.f;

    // ldmatrix lane addresses (bytes): 16 rows x {0,16B}
    const uint32_t aLane = (uint32_t)(wm + (lane & 15)) * 80 + (uint32_t)(lane & 16);
    const uint32_t bLane = 10240 + (uint32_t)(wn + (lane & 15)) * 80 + (uint32_t)(lane & 16);

    load(0); cp_commit();
    load(1); cp_commit();
    load(2); cp_commit();

    uint32_t af0[4][4], bq0[2][4];   // prefetched ks=0 fragments (live across barrier)
    uint32_t af1[4][4], bq1[2][4];   // in-loop ks=1 fragments

    cp_wait<2>();                    // stage 0 landed (own groups)
    __syncthreads();                 // publish stage 0
#pragma unroll
    for (int i = 0; i < 4; i++) ldsm4(af0[i], sb + aLane + i * 1280);
    ldsm4(bq0[0], sb + bLane);
    ldsm4(bq0[1], sb + bLane + 16 * 80);

    const int NT = K / 32;   // 32
    for (int kb = 0; kb < NT; kb++) {
        cp_wait<1>();                // completes group kb+1 (for tail prefetch)
        __syncthreads();             // publishes stage kb+1; licenses overwrite of kb-1
        if (kb + 3 < NT) load(kb + 3);
        cp_commit();

        const uint32_t st = sb + (uint32_t)(kb & 3) * GSTG_BYTES;
        // ks=1 fragment loads (independent of ks=0 MMAs below)
#pragma unroll
        for (int i = 0; i < 4; i++) ldsm4(af1[i], st + aLane + i * 1280 + 32);
        ldsm4(bq1[0], st + bLane + 32);
        ldsm4(bq1[1], st + bLane + 16 * 80 + 32);

        // MMAs for ks=0 using prefetched frags — overlap the LDSMs above
#pragma unroll
        for (int i = 0; i < 4; i++) {
            mma16(acc[i][0], af0[i][0], af0[i][1], af0[i][2], af0[i][3], bq0[0][0], bq0[0][2]);
            mma16(acc[i][1], af0[i][0], af0[i][1], af0[i][2], af0[i][3], bq0[0][1], bq0[0][3]);
            mma16(acc[i][2], af0[i][0], af0[i][1], af0[i][2], af0[i][3], bq0[1][0], bq0[1][2]);
            mma16(acc[i][3], af0[i][0], af0[i][1], af0[i][2], af0[i][3], bq0[1][1], bq0[1][3]);
        }
        // MMAs for ks=1
#pragma unroll
        for (int i = 0; i < 4; i++) {
            mma16(acc[i][0], af1[i][0], af1[i][1], af1[i][2], af1[i][3], bq1[0][0], bq1[0][2]);
            mma16(acc[i][1], af1[i][0], af1[i][1], af1[i][2], af1[i][3], bq1[0][1], bq1[0][3]);
            mma16(acc[i][2], af1[i][0], af1[i][1], af1[i][2], af1[i][3], bq1[1][0], bq1[1][2]);
            mma16(acc[i][3], af1[i][0], af1[i][1], af1[i][2], af1[i][3], bq1[1][1], bq1[1][3]);
        }

        // tail prefetch: ks=0 fragments of stage kb+1 (published by this barrier)
        if (kb + 1 < NT) {
            const uint32_t sn = sb + (uint32_t)((kb + 1) & 3) * GSTG_BYTES;
#pragma unroll
            for (int i = 0; i < 4; i++) ldsm4(af0[i], sn + aLane + i * 1280);
            ldsm4(bq0[0], sn + bLane);
            ldsm4(bq0[1], sn + bLane + 16 * 80);
        }
    }

    // epilogue: bias + store (half2 or float2)
#pragma unroll
    for (int i = 0; i < 4; i++) {
        const int row0 = bm + wm + 16 * i + r;
#pragma unroll
        for (int j = 0; j < 4; j++) {
            const int col = bn + wn + 8 * j + 2 * cc;
            const float b0 = bias[col], b1 = bias[col + 1];
            float v00 = acc[i][j][0] + b0, v01 = acc[i][j][1] + b1;
            float v10 = acc[i][j][2] + b0, v11 = acc[i][j][3] + b1;
            if (HALF_OUT) {
                __half* C = (__half*)Cp;
                *(uint32_t*)&C[(size_t)row0 * NTOT + col]       = packh2(v00, v01);
                *(uint32_t*)&C[(size_t)(row0 + 8) * NTOT + col] = packh2(v10, v11);
            } else {
                float* C = (float*)Cp;
                *(float2*)&C[(size_t)row0 * NTOT + col]       = make_float2(v00, v01);
                *(float2*)&C[(size_t)(row0 + 8) * NTOT + col] = make_float2(v10, v11);
            }
        }
    }
}

// ---------------------------------------------------------------------------
// Flash attention, fp16 mma.sync m16n8k16 (unchanged from R16).
// ---------------------------------------------------------------------------
#define KROWH 72
#define KBUFH (64 * KROWH)

__global__ void __launch_bounds__(256, 2) k_attention() {
    __shared__ __half Ks[2][64][KROWH];
    __shared__ __half Vs[2][64][KROWH];

    const int tid  = threadIdx.x;
    const int lane = tid & 31;
    const int warp = tid >> 5;
    const int qt = blockIdx.x;
    const int h  = blockIdx.y;
    const int b  = blockIdx.z;
    const int r  = lane >> 2;
    const int c  = lane & 3;

    const float qscale = 0.125f * 1.4426950408889634f;
    uint32_t qf[4][4];
    {
        const __half* Qp = g_qkv + (size_t)(b * SEQ + qt * 128 + warp * 16) * QKV_N + h * HEAD_DIM;
#pragma unroll
        for (int ks = 0; ks < 4; ks++) {
#pragma unroll
            for (int half8 = 0; half8 < 2; half8++) {
                const int kc = 16 * ks + 8 * half8 + 2 * c;
                float2 f0 = __half22float2(*(const __half2*)&Qp[(size_t)r       * QKV_N + kc]);
                float2 f1 = __half22float2(*(const __half2*)&Qp[(size_t)(r + 8) * QKV_N + kc]);
                qf[ks][2 * half8 + 0] = packh2(f0.x * qscale, f0.y * qscale);
                qf[ks][2 * half8 + 1] = packh2(f1.x * qscale, f1.y * qscale);
            }
        }
    }

    const int srow = tid >> 2;
    const int sc0  = (tid & 3) * 16;
    const __half* kbase = g_qkv + (size_t)(b * SEQ) * QKV_N + HIDDEN + h * HEAD_DIM + sc0;

    auto load_chunk = [&](int ct, int buf) {
        const __half* kp = kbase + (size_t)(ct * 64 + srow) * QKV_N;
        const __half* vp = kp + HIDDEN;
        const uint32_t kd = smem_u32(&Ks[buf][srow][sc0]);
        const uint32_t vd = smem_u32(&Vs[buf][srow][sc0]);
        cp16(kd,      kp);
        cp16(kd + 16, kp + 8);
        cp16(vd,      vp);
        cp16(vd + 16, vp + 8);
    };

    float m0 = -INFINITY, m1 = -INFINITY, l0 = 0.f, l1 = 0.f;
    float o[8][4];
#pragma unroll
    for (int j = 0; j < 8; j++)
#pragma unroll
        for (int q = 0; q < 4; q++) o[j][q] = 0.f;

    const uint32_t lmLane = (uint32_t)(lane & 15) * 144 + (uint32_t)(lane & 16);

    load_chunk(0, 0);
    cp_commit();

    for (int ct = 0; ct < 16; ct++) {
        const int buf = ct & 1;
        cp_wait<0>();
        __syncthreads();
        if (ct + 1 < 16) load_chunk(ct + 1, buf ^ 1);
        cp_commit();

        const uint32_t Kbase = smem_u32(&Ks[buf][0][0]) + lmLane;
        const uint32_t Vbase = smem_u32(&Vs[buf][0][0]) + lmLane;

        float s[8][4];
#pragma unroll
        for (int j = 0; j < 8; j++)
#pragma unroll
            for (int q = 0; q < 4; q++) s[j][q] = 0.f;

#pragma unroll
        for (int ks = 0; ks < 4; ks++) {
#pragma unroll
            for (int j2 = 0; j2 < 4; j2++) {
                uint32_t kq[4];
                ldsm4(kq, Kbase + (uint32_t)j2 * (16 * 144) + ks * 32);
                mma16(s[2 * j2],     qf[ks][0], qf[ks][1], qf[ks][2], qf[ks][3], kq[0], kq[2]);
                mma16(s[2 * j2 + 1], qf[ks][0], qf[ks][1], qf[ks][2], qf[ks][3], kq[1], kq[3]);
            }
        }

        float mx0 = -INFINITY, mx1 = -INFINITY;
#pragma unroll
        for (int j = 0; j < 8; j++) {
            mx0 = fmaxf(mx0, fmaxf(s[j][0], s[j][1]));
            mx1 = fmaxf(mx1, fmaxf(s[j][2], s[j][3]));
        }
#pragma unroll
        for (int off = 1; off < 4; off <<= 1) {
            mx0 = fmaxf(mx0, __shfl_xor_sync(0xffffffffu, mx0, off));
            mx1 = fmaxf(mx1, __shfl_xor_sync(0xffffffffu, mx1, off));
        }
        const float nm0 = fmaxf(m0, mx0), nm1 = fmaxf(m1, mx1);
        const float cor0 = ex2(m0 - nm0), cor1 = ex2(m1 - nm1);
        m0 = nm0; m1 = nm1;
        float rs0 = 0.f, rs1 = 0.f;
#pragma unroll
        for (int j = 0; j < 8; j++) {
            s[j][0] = ex2(s[j][0] - nm0);
            s[j][1] = ex2(s[j][1] - nm0);
            s[j][2] = ex2(s[j][2] - nm1);
            s[j][3] = ex2(s[j][3] - nm1);
            rs0 += s[j][0] + s[j][1];
            rs1 += s[j][2] + s[j][3];
        }
#pragma unroll
        for (int off = 1; off < 4; off <<= 1) {
            rs0 += __shfl_xor_sync(0xffffffffu, rs0, off);
            rs1 += __shfl_xor_sync(0xffffffffu, rs1, off);
        }
        l0 = l0 * cor0 + rs0;
        l1 = l1 * cor1 + rs1;
#pragma unroll
        for (int j = 0; j < 8; j++) {
            o[j][0] *= cor0; o[j][1] *= cor0;
            o[j][2] *= cor1; o[j][3] *= cor1;
        }

#pragma unroll
        for (int kt = 0; kt < 4; kt++) {
            const uint32_t a0 = packh2(s[2 * kt][0],     s[2 * kt][1]);
            const uint32_t a1 = packh2(s[2 * kt][2],     s[2 * kt][3]);
            const uint32_t a2 = packh2(s[2 * kt + 1][0], s[2 * kt + 1][1]);
            const uint32_t a3 = packh2(s[2 * kt + 1][2], s[2 * kt + 1][3]);
#pragma unroll
            for (int d4 = 0; d4 < 4; d4++) {
                uint32_t vq[4];
                ldsm4t(vq, Vbase + (uint32_t)kt * (16 * 144) + d4 * 32);
                mma16(o[2 * d4],     a0, a1, a2, a3, vq[0], vq[1]);
                mma16(o[2 * d4 + 1], a0, a1, a2, a3, vq[2], vq[3]);
            }
        }
    }

    const float inv0 = 1.f / l0, inv1 = 1.f / l1;
    const size_t gq = (size_t)(b * SEQ + qt * 128 + warp * 16);
#pragma unroll
    for (int j = 0; j < 8; j++) {
        const int col = h * HEAD_DIM + 8 * j + 2 * c;
        *(uint32_t*)&g_att[(gq + r) * HIDDEN + col]     = packh2(o[j][0] * inv0, o[j][1] * inv0);
        *(uint32_t*)&g_att[(gq + r + 8) * HIDDEN + col] = packh2(o[j][2] * inv1, o[j][3] * inv1);
    }
}

// ---------------------------------------------------------------------------
extern "C" void kernel_launch(void* const* d_in, const int* in_sizes, int n_in,
                              void* d_out, int out_size) {
    const float* query = (const float*)d_in[0];
    const float* w_qkv = (const float*)d_in[1];
    const float* b_qkv = (const float*)d_in[2];
    const float* w_o   = (const float*)d_in[3];
    const float* b_o   = (const float*)d_in[4];
    float* out = (float*)d_out;

    __half *gx, *gw1t, *gw2t, *gqkv, *gatt;
    cudaGetSymbolAddress((void**)&gx,   g_x);
    cudaGetSymbolAddress((void**)&gw1t, g_w1t);
    cudaGetSymbolAddress((void**)&gw2t, g_w2t);
    cudaGetSymbolAddress((void**)&gqkv, g_qkv);
    cudaGetSymbolAddress((void**)&gatt, g_att);

    cudaFuncSetAttribute(gemm_h<QKV_N, true>,   cudaFuncAttributeMaxDynamicSharedMemorySize, GEMM_SMEM);
    cudaFuncSetAttribute(gemm_h<HIDDEN, false>, cudaFuncAttributeMaxDynamicSharedMemorySize, GEMM_SMEM);

    // prep: cvt X; transpose+cvt weights
    {
        int n4x = MTOT * HIDDEN / 4;
        k_cvt_half<<<(n4x + 255) / 256, 256>>>(query, gx, n4x);
        dim3 tb(32, 8);
        k_transpose_h<<<dim3(QKV_N / 32, HIDDEN / 32), tb>>>(w_qkv, gw1t, HIDDEN, QKV_N);
        k_transpose_h<<<dim3(HIDDEN / 32, HIDDEN / 32), tb>>>(w_o, gw2t, HIDDEN, HIDDEN);
    }

    // QKV GEMM (fp16 out -> feeds attention directly)
    gemm_h<QKV_N, true><<<dim3(QKV_N / 128, MTOT / 128), 256, GEMM_SMEM>>>(gx, gw1t, b_qkv, gqkv);

    // flash attention
    k_attention<<<dim3(SEQ / 128, HEADS, BATCH), 256>>>();

    // output GEMM (fp32 out)
    gemm_h<HIDDEN, false><<<dim3(HIDDEN / 128, MTOT / 128), 256, GEMM_SMEM>>>(gatt, gw2t, b_o, out);
}